// round 12
// baseline (speedup 1.0000x reference)
#include <cuda_runtime.h>
#include <cstdint>

// ---- static problem config ----
#define B_   2
#define N_   6
#define D_   48
#define FH_  16
#define FW_  44
#define C_   80
#define NX_  256
#define NY_  256
#define NPRIME (B_*N_*D_*FH_*FW_)       // 405504 points
#define NGROUP (B_*N_*D_*FW_)           // 25344 (b,n,d,w) groups of 16 h-points
#define CVEC   (C_/4)                   // 20 float4 per point row
#define PLANE  (NY_*NX_)                // 65536
#define OUT_F4 (B_*C_*PLANE/4)          // 2,621,440 float4
#define ZBLOCKS (OUT_F4/1024)           // 2560 blocks zero 1024 f4 each
#define GBLOCKS ((NPRIME+255)/256)      // 1584 geom blocks

// ---- device scratch ----
__device__ int g_flat[NPRIME];          // [group][h] voxel id or -1

// ---------------------------------------------------------------------------
__device__ __forceinline__ void inv3(const float* m, float* o) {
    float a=m[0], b=m[1], c=m[2];
    float d=m[3], e=m[4], f=m[5];
    float g=m[6], h=m[7], i=m[8];
    float A  =  (e*i - f*h);
    float Bc = -(d*i - f*g);
    float Cc =  (d*h - e*g);
    float det = a*A + b*Bc + c*Cc;
    float r = 1.0f / det;
    o[0] = A*r;            o[1] = (c*h - b*i)*r;  o[2] = (b*f - c*e)*r;
    o[3] = Bc*r;           o[4] = (a*i - c*g)*r;  o[5] = (c*d - a*f)*r;
    o[6] = Cc*r;           o[7] = (b*g - a*h)*r;  o[8] = (a*e - b*d)*r;
}

// ---------------------------------------------------------------------------
// Fused: blocks [0, ZBLOCKS) zero the output; remaining blocks do per-point
// geometry (camera transform recomputed inline; matrices broadcast from L1).
// g_flat written transposed as [group][h].
__global__ void zero_geom_kernel(float4* __restrict__ out4,
                                 const float* __restrict__ rots,
                                 const float* __restrict__ trans,
                                 const float* __restrict__ intrins,
                                 const float* __restrict__ post_rots,
                                 const float* __restrict__ post_trans) {
    int blk = blockIdx.x;
    if (blk < ZBLOCKS) {
        const float4 z = make_float4(0.f, 0.f, 0.f, 0.f);
        int base = blk * 1024 + threadIdx.x;
        #pragma unroll
        for (int i = 0; i < 4; i++) out4[base + i * 256] = z;
        return;
    }
    int p = (blk - ZBLOCKS) * 256 + threadIdx.x;
    if (p >= NPRIME) return;

    int w  = p % FW_;
    int h  = (p / FW_) % FH_;
    int d  = (p / (FW_*FH_)) % D_;
    int bn = p / (FW_*FH_*D_);
    int b  = bn / N_;

    float invP[9], invK[9], comb[9];
    inv3(post_rots + bn*9, invP);
    inv3(intrins  + bn*9, invK);
    const float* R = rots + bn*9;
    #pragma unroll
    for (int r_ = 0; r_ < 3; r_++)
        #pragma unroll
        for (int j = 0; j < 3; j++) {
            float s = 0.0f;
            #pragma unroll
            for (int k = 0; k < 3; k++) s += R[r_*3+k] * invK[k*3+j];
            comb[r_*3+j] = s;
        }
    float tx = trans[bn*3+0], ty = trans[bn*3+1], tz = trans[bn*3+2];
    float ptx = post_trans[bn*3+0], pty = post_trans[bn*3+1], ptz = post_trans[bn*3+2];

    float xs = (float)w * (float)(703.0 / 43.0);
    float ys = (float)h * 17.0f;
    float ds = 2.0f + (float)(56.0 / 48.0) * (float)d;

    float px = xs - ptx;
    float py = ys - pty;
    float pz = ds - ptz;
    float qx = invP[0]*px + invP[1]*py + invP[2]*pz;
    float qy = invP[3]*px + invP[4]*py + invP[5]*pz;
    float qz = invP[6]*px + invP[7]*py + invP[8]*pz;
    qx *= qz; qy *= qz;
    float rx = comb[0]*qx + comb[1]*qy + comb[2]*qz + tx;
    float ry = comb[3]*qx + comb[4]*qy + comb[5]*qz + ty;
    float rz = comb[6]*qx + comb[7]*qy + comb[8]*qz + tz;

    int gx = (int)((rx - (-51.2f)) / 0.4f);
    int gy = (int)((ry - (-51.2f)) / 0.4f);
    int gz = (int)((rz - (-10.0f)) / 20.0f);

    bool kept = (gx >= 0) & (gx < NX_) & (gy >= 0) & (gy < NY_) & (gz >= 0) & (gz < 1);
    int flat = kept ? ((b * NY_ + gy) * NX_ + gx) : -1;

    int group = (bn * D_ + d) * FW_ + w;
    g_flat[group * FH_ + h] = flat;
}

// ---------------------------------------------------------------------------
// Emit acc (channels 4k..4k+3) for voxel 'flat' directly into [B,C,NY,NX].
__device__ __forceinline__ void flush_acc(float* __restrict__ out, int flat, int k,
                                          const float4& acc) {
    int b   = flat >> 16;             // flat / PLANE  (PLANE = 65536)
    int vox = flat & (PLANE - 1);
    float* dst = out + ((size_t)(b * C_ + 4*k)) * PLANE + vox;
    asm volatile("red.global.add.f32 [%0], %1;" :: "l"(dst),           "f"(acc.x) : "memory");
    asm volatile("red.global.add.f32 [%0], %1;" :: "l"(dst + PLANE),   "f"(acc.y) : "memory");
    asm volatile("red.global.add.f32 [%0], %1;" :: "l"(dst + 2*PLANE), "f"(acc.z) : "memory");
    asm volatile("red.global.add.f32 [%0], %1;" :: "l"(dst + 3*PLANE), "f"(acc.w) : "memory");
}

__device__ __forceinline__ bool eq4(const int4& a, const int4& b) {
    return (a.x == b.x) & (a.y == b.y) & (a.z == b.z) & (a.w == b.w);
}

// One thread per (group, chunk): sums the group's 16 h-points by voxel-id run,
// one reduction per run. Uniformity tested at int4 level so the hot path keeps
// register pressure <=32 (8 blocks/SM). __ldcs keeps the accumulator L2-resident.
__global__ void __launch_bounds__(256, 8) hsum_scatter_kernel(
        const float4* __restrict__ x4, float* __restrict__ out) {
    int t = blockIdx.x * 256 + threadIdx.x;   // exact grid: NGROUP*CVEC
    int g = t / CVEC;
    int k = t - g * CVEC;

    int w   = g % FW_;
    int dnb = g / FW_;                 // bn*D + d
    int base_p = dnb * (FH_*FW_) + w;  // point index at h=0

    const int4* fp = (const int4*)(g_flat + g * FH_);
    int4 fa = fp[0], fb = fp[1], fc = fp[2], fd = fp[3];

    bool uniform = (fa.x == fa.y) & (fa.x == fa.z) & (fa.x == fa.w)
                 & eq4(fa, fb) & eq4(fa, fc) & eq4(fa, fd);

    const float4* xp = x4 + (size_t)base_p * CVEC + k;
    const size_t hstride = (size_t)FW_ * CVEC;

    if (uniform) {
        if (fa.x < 0) return;
        float4 acc = make_float4(0.f, 0.f, 0.f, 0.f);
        #pragma unroll
        for (int h = 0; h < FH_; h++) {
            float4 a = __ldcs(xp + h * hstride);
            acc.x += a.x; acc.y += a.y; acc.z += a.z; acc.w += a.w;
        }
        flush_acc(out, fa.x, k, acc);
    } else {
        int fl[FH_] = { fa.x, fa.y, fa.z, fa.w, fb.x, fb.y, fb.z, fb.w,
                        fc.x, fc.y, fc.z, fc.w, fd.x, fd.y, fd.z, fd.w };
        float4 acc = make_float4(0.f, 0.f, 0.f, 0.f);
        int cur = -1;
        #pragma unroll
        for (int h = 0; h < FH_; h++) {
            int f = fl[h];
            if (f < 0) continue;
            if (f != cur) {
                if (cur >= 0) flush_acc(out, cur, k, acc);
                acc = make_float4(0.f, 0.f, 0.f, 0.f);
                cur = f;
            }
            float4 a = __ldcs(xp + h * hstride);
            acc.x += a.x; acc.y += a.y; acc.z += a.z; acc.w += a.w;
        }
        if (cur >= 0) flush_acc(out, cur, k, acc);
    }
}

// ---------------------------------------------------------------------------
extern "C" void kernel_launch(void* const* d_in, const int* in_sizes, int n_in,
                              void* d_out, int out_size) {
    const float* x          = (const float*)d_in[0];
    const float* rots       = (const float*)d_in[1];
    const float* trans      = (const float*)d_in[2];
    const float* intrins    = (const float*)d_in[3];
    const float* post_rots  = (const float*)d_in[4];
    const float* post_trans = (const float*)d_in[5];
    float* out = (float*)d_out;

    zero_geom_kernel<<<ZBLOCKS + GBLOCKS, 256>>>(
        (float4*)out, rots, trans, intrins, post_rots, post_trans);
    hsum_scatter_kernel<<<(NGROUP * CVEC) / 256, 256>>>((const float4*)x, out);
}

// round 13
// speedup vs baseline: 1.0911x; 1.0911x over previous
#include <cuda_runtime.h>
#include <cstdint>

// ---- static problem config ----
#define B_   2
#define N_   6
#define D_   48
#define FH_  16
#define FW_  44
#define C_   80
#define NX_  256
#define NY_  256
#define NPRIME (B_*N_*D_*FH_*FW_)       // 405504 points
#define NGROUP (B_*N_*D_*FW_)           // 25344 (b,n,d,w) groups of 16 h-points
#define CVEC   (C_/4)                   // 20 float4 per point row
#define PLANE  (NY_*NX_)                // 65536
#define OUT_F4 (B_*C_*PLANE/4)          // 2,621,440 float4
#define ZBLOCKS (OUT_F4/1024)           // 2560 blocks zero 1024 f4 each
#define GBLOCKS ((NPRIME+255)/256)      // 1584 geom blocks

// ---- device scratch ----
__device__ int g_flat[NPRIME];          // [group][h] voxel id or -1

// ---------------------------------------------------------------------------
__device__ __forceinline__ void inv3(const float* m, float* o) {
    float a=m[0], b=m[1], c=m[2];
    float d=m[3], e=m[4], f=m[5];
    float g=m[6], h=m[7], i=m[8];
    float A  =  (e*i - f*h);
    float Bc = -(d*i - f*g);
    float Cc =  (d*h - e*g);
    float det = a*A + b*Bc + c*Cc;
    float r = 1.0f / det;
    o[0] = A*r;            o[1] = (c*h - b*i)*r;  o[2] = (b*f - c*e)*r;
    o[3] = Bc*r;           o[4] = (a*i - c*g)*r;  o[5] = (c*d - a*f)*r;
    o[6] = Cc*r;           o[7] = (b*g - a*h)*r;  o[8] = (a*e - b*d)*r;
}

// ---------------------------------------------------------------------------
// Fused: blocks [0, ZBLOCKS) zero the output; remaining blocks do per-point
// geometry (camera transform recomputed inline; matrices broadcast from L1).
// g_flat written transposed as [group][h].
__global__ void zero_geom_kernel(float4* __restrict__ out4,
                                 const float* __restrict__ rots,
                                 const float* __restrict__ trans,
                                 const float* __restrict__ intrins,
                                 const float* __restrict__ post_rots,
                                 const float* __restrict__ post_trans) {
    int blk = blockIdx.x;
    if (blk < ZBLOCKS) {
        const float4 z = make_float4(0.f, 0.f, 0.f, 0.f);
        int base = blk * 1024 + threadIdx.x;
        #pragma unroll
        for (int i = 0; i < 4; i++) out4[base + i * 256] = z;
        return;
    }
    int p = (blk - ZBLOCKS) * 256 + threadIdx.x;
    if (p >= NPRIME) return;

    int w  = p % FW_;
    int h  = (p / FW_) % FH_;
    int d  = (p / (FW_*FH_)) % D_;
    int bn = p / (FW_*FH_*D_);
    int b  = bn / N_;

    float invP[9], invK[9], comb[9];
    inv3(post_rots + bn*9, invP);
    inv3(intrins  + bn*9, invK);
    const float* R = rots + bn*9;
    #pragma unroll
    for (int r_ = 0; r_ < 3; r_++)
        #pragma unroll
        for (int j = 0; j < 3; j++) {
            float s = 0.0f;
            #pragma unroll
            for (int k = 0; k < 3; k++) s += R[r_*3+k] * invK[k*3+j];
            comb[r_*3+j] = s;
        }
    float tx = trans[bn*3+0], ty = trans[bn*3+1], tz = trans[bn*3+2];
    float ptx = post_trans[bn*3+0], pty = post_trans[bn*3+1], ptz = post_trans[bn*3+2];

    float xs = (float)w * (float)(703.0 / 43.0);
    float ys = (float)h * 17.0f;
    float ds = 2.0f + (float)(56.0 / 48.0) * (float)d;

    float px = xs - ptx;
    float py = ys - pty;
    float pz = ds - ptz;
    float qx = invP[0]*px + invP[1]*py + invP[2]*pz;
    float qy = invP[3]*px + invP[4]*py + invP[5]*pz;
    float qz = invP[6]*px + invP[7]*py + invP[8]*pz;
    qx *= qz; qy *= qz;
    float rx = comb[0]*qx + comb[1]*qy + comb[2]*qz + tx;
    float ry = comb[3]*qx + comb[4]*qy + comb[5]*qz + ty;
    float rz = comb[6]*qx + comb[7]*qy + comb[8]*qz + tz;

    int gx = (int)((rx - (-51.2f)) / 0.4f);
    int gy = (int)((ry - (-51.2f)) / 0.4f);
    int gz = (int)((rz - (-10.0f)) / 20.0f);

    bool kept = (gx >= 0) & (gx < NX_) & (gy >= 0) & (gy < NY_) & (gz >= 0) & (gz < 1);
    int flat = kept ? ((b * NY_ + gy) * NX_ + gx) : -1;

    int group = (bn * D_ + d) * FW_ + w;
    g_flat[group * FH_ + h] = flat;
}

// ---------------------------------------------------------------------------
// Emit acc (channels 4k..4k+3) for voxel 'flat' directly into [B,C,NY,NX].
__device__ __forceinline__ void flush_acc(float* __restrict__ out, int flat, int k,
                                          const float4& acc) {
    int b   = flat >> 16;             // flat / PLANE  (PLANE = 65536)
    int vox = flat & (PLANE - 1);
    float* dst = out + ((size_t)(b * C_ + 4*k)) * PLANE + vox;
    asm volatile("red.global.add.f32 [%0], %1;" :: "l"(dst),           "f"(acc.x) : "memory");
    asm volatile("red.global.add.f32 [%0], %1;" :: "l"(dst + PLANE),   "f"(acc.y) : "memory");
    asm volatile("red.global.add.f32 [%0], %1;" :: "l"(dst + 2*PLANE), "f"(acc.z) : "memory");
    asm volatile("red.global.add.f32 [%0], %1;" :: "l"(dst + 3*PLANE), "f"(acc.w) : "memory");
}

// One thread per (group, chunk). FAST PATH: at most one distinct non-negative
// voxel id among the 16 h-points (covers "all same" AND "same + some dropped").
// All 16 loads issued unconditionally & branch-free (MLP=16), masked accumulate,
// single flush. SLOW PATH (genuinely multi-voxel, rare): run-length flushes.
__global__ void __launch_bounds__(256, 6) hsum_scatter_kernel(
        const float4* __restrict__ x4, float* __restrict__ out) {
    int t = blockIdx.x * 256 + threadIdx.x;   // exact grid: NGROUP*CVEC
    int g = t / CVEC;
    int k = t - g * CVEC;

    int w   = g % FW_;
    int dnb = g / FW_;                 // bn*D + d
    int base_p = dnb * (FH_*FW_) + w;  // point index at h=0

    const int4* fp = (const int4*)(g_flat + g * FH_);
    int4 fa = fp[0], fb = fp[1], fc = fp[2], fd = fp[3];
    int fl[FH_] = { fa.x, fa.y, fa.z, fa.w, fb.x, fb.y, fb.z, fb.w,
                    fc.x, fc.y, fc.z, fc.w, fd.x, fd.y, fd.z, fd.w };

    // F = max id; fast iff every id is F or -1
    int F = fl[0];
    #pragma unroll
    for (int h = 1; h < FH_; h++) F = max(F, fl[h]);
    if (F < 0) return;                 // nothing kept in this group

    bool fast = true;
    #pragma unroll
    for (int h = 0; h < FH_; h++) fast &= ((fl[h] == F) | (fl[h] < 0));

    const float4* xp = x4 + (size_t)base_p * CVEC + k;
    const size_t hstride = (size_t)FW_ * CVEC;

    if (fast) {
        float4 acc = make_float4(0.f, 0.f, 0.f, 0.f);
        #pragma unroll
        for (int h = 0; h < FH_; h++) {
            float4 a = __ldcs(xp + h * hstride);      // unconditional: full MLP
            float m = (fl[h] >= 0) ? 1.0f : 0.0f;     // branch-free mask
            acc.x += m * a.x; acc.y += m * a.y;
            acc.z += m * a.z; acc.w += m * a.w;
        }
        flush_acc(out, F, k, acc);
    } else {
        float4 acc = make_float4(0.f, 0.f, 0.f, 0.f);
        int cur = -1;
        #pragma unroll
        for (int h = 0; h < FH_; h++) {
            int f = fl[h];
            if (f < 0) continue;
            if (f != cur) {
                if (cur >= 0) flush_acc(out, cur, k, acc);
                acc = make_float4(0.f, 0.f, 0.f, 0.f);
                cur = f;
            }
            float4 a = __ldcs(xp + h * hstride);
            acc.x += a.x; acc.y += a.y; acc.z += a.z; acc.w += a.w;
        }
        if (cur >= 0) flush_acc(out, cur, k, acc);
    }
}

// ---------------------------------------------------------------------------
extern "C" void kernel_launch(void* const* d_in, const int* in_sizes, int n_in,
                              void* d_out, int out_size) {
    const float* x          = (const float*)d_in[0];
    const float* rots       = (const float*)d_in[1];
    const float* trans      = (const float*)d_in[2];
    const float* intrins    = (const float*)d_in[3];
    const float* post_rots  = (const float*)d_in[4];
    const float* post_trans = (const float*)d_in[5];
    float* out = (float*)d_out;

    zero_geom_kernel<<<ZBLOCKS + GBLOCKS, 256>>>(
        (float4*)out, rots, trans, intrins, post_rots, post_trans);
    hsum_scatter_kernel<<<(NGROUP * CVEC) / 256, 256>>>((const float4*)x, out);
}